// round 10
// baseline (speedup 1.0000x reference)
#include <cuda_runtime.h>
#include <cuda_bf16.h>
#include <cstdint>

#define Bb 32
#define Dd 2048
#define Tt 512
#define Kk 512
#define Nn (Bb*Tt)            // 16384
#define BDT (Bb*Dd*Tt)        // 33554432
#define OH1_OFF BDT
#define BAR_OFF (BDT + Nn)
#define OH2_OFF (2*BDT + Nn)
#define MARGIN 2e-3f

// ---------------- scratch (device globals; allocation-free) ----------------
__device__ __nv_bfloat16 g_a0[(size_t)Nn * Dd];   // z bf16, n-major
__device__ float         g_at[(size_t)Nn * Dd];   // z fp32, n-major (exact)
__device__ __nv_bfloat16 g_b0[(size_t)Kk * Dd];   // codebook bf16
__device__ float g_dots[(size_t)Nn * Kk];         // approx scores (32 MB)
__device__ float g_S[Nn];
__device__ float g_C2[Kk];
__device__ int   g_idx[Nn];

__device__ __forceinline__ uint32_t smem_u32(const void* p) {
    uint32_t a;
    asm("{ .reg .u64 t; cvta.to.shared.u64 t, %1; cvt.u32.u64 %0, t; }" : "=r"(a) : "l"(p));
    return a;
}
__device__ __forceinline__ uint32_t sw_off(int r, int cbyte) {
    return (uint32_t)(r * 128 + (cbyte ^ ((r & 7) << 4)));
}

#define LDSM4(f, addr) \
    asm volatile("ldmatrix.sync.aligned.m8n8.x4.shared.b16 {%0,%1,%2,%3}, [%4];" \
        : "=r"((f)[0]), "=r"((f)[1]), "=r"((f)[2]), "=r"((f)[3]) : "r"(addr))

#define MMA16816(d, a, br0, br1) \
    asm volatile("mma.sync.aligned.m16n8k16.row.col.f32.bf16.bf16.f32 " \
        "{%0,%1,%2,%3}, {%4,%5,%6,%7}, {%8,%9}, {%0,%1,%2,%3};" \
        : "+f"((d)[0]), "+f"((d)[1]), "+f"((d)[2]), "+f"((d)[3]) \
        : "r"((a)[0]), "r"((a)[1]), "r"((a)[2]), "r"((a)[3]), "r"(br0), "r"(br1))

// ---------------------------------------------------------------------------
// codebook: C2 + bf16 copy (validated)
// ---------------------------------------------------------------------------
__global__ void k_prep_cb(const float* __restrict__ cb) {
    int k = blockIdx.x;
    const float4* row = (const float4*)(cb + (size_t)k * Dd);
    float s = 0.f;
    for (int i = threadIdx.x; i < Dd / 4; i += 256) {
        float4 v = row[i];
        s += v.x * v.x + v.y * v.y + v.z * v.z + v.w * v.w;
        __nv_bfloat16 h[4];
        h[0] = __float2bfloat16(v.x); h[1] = __float2bfloat16(v.y);
        h[2] = __float2bfloat16(v.z); h[3] = __float2bfloat16(v.w);
        *(uint2*)&g_b0[(size_t)k * Dd + 4 * i] = *(uint2*)h;
    }
    __shared__ float sm[256];
    sm[threadIdx.x] = s;
    __syncthreads();
    for (int o = 128; o; o >>= 1) {
        if (threadIdx.x < o) sm[threadIdx.x] += sm[threadIdx.x + o];
        __syncthreads();
    }
    if (threadIdx.x == 0) g_C2[k] = sm[0];
}

// ---------------------------------------------------------------------------
// fused: z (B,D,T) -> n-major bf16 + n-major fp32 + S[n]  (validated)
// ---------------------------------------------------------------------------
__global__ void __launch_bounds__(256) k_prep_z_s(const float* __restrict__ z) {
    __shared__ float s[64][33];
    __shared__ float red[32][9];
    int t0 = blockIdx.x * 32;
    int b  = blockIdx.y;
    const float* zp = z + (size_t)b * Dd * Tt + t0;

    int nl = threadIdx.x >> 3;
    int dc = (threadIdx.x & 7) * 8;
    size_t nrow = (size_t)(b * Tt + t0 + nl) * Dd;
    float Sacc = 0.f;

    for (int dt = 0; dt < 32; dt++) {
        int d0 = dt * 64;
#pragma unroll
        for (int i = 0; i < 8; i++) {
            int e = i * 256 + threadIdx.x;
            int dr = e >> 5, tc = e & 31;
            s[dr][tc] = zp[(size_t)(d0 + dr) * Tt + tc];
        }
        __syncthreads();

        float f[8];
        __nv_bfloat16 h[8];
#pragma unroll
        for (int j = 0; j < 8; j++) {
            f[j] = s[dc + j][nl];
            h[j] = __float2bfloat16(f[j]);
            Sacc += f[j] * f[j];
        }
        *(float4*)&g_at[nrow + d0 + dc]     = *(float4*)(f + 0);
        *(float4*)&g_at[nrow + d0 + dc + 4] = *(float4*)(f + 4);
        *(uint4*)&g_a0[nrow + d0 + dc]      = *(uint4*)h;
        __syncthreads();
    }

    red[nl][threadIdx.x & 7] = Sacc;
    __syncthreads();
    if (threadIdx.x < 32) {
        float t = 0.f;
#pragma unroll
        for (int g = 0; g < 8; g++) t += red[threadIdx.x][g];
        g_S[b * Tt + t0 + threadIdx.x] = t;
    }
}

// ---------------------------------------------------------------------------
// single-pass bf16 mma.sync GEMM -> g_dots  (exact R4/R7 kernel, validated)
// ---------------------------------------------------------------------------
#define TILE_BYTES 16384
#define STAGE_BYTES (2*TILE_BYTES)
#define SM_SZ (3*STAGE_BYTES)      // 98304

__global__ void __launch_bounds__(256) k_gemm_mma() {
    extern __shared__ char sm[];
    const int tid  = threadIdx.x;
    const int lane = tid & 31, wid = tid >> 5;
    const int mw = wid & 1, nw = wid >> 1;
    const int n0 = blockIdx.y * 128;
    const int k0 = blockIdx.x * 128;

    const __nv_bfloat16* srcs[2];
    srcs[0] = g_a0 + (size_t)n0 * Dd;
    srcs[1] = g_b0 + (size_t)k0 * Dd;

    const uint32_t smbase = smem_u32(sm);

    auto stage_load = [&](int kt, int slot) {
        const int d0 = kt * 64;
        const uint32_t sbase = smbase + slot * STAGE_BYTES;
#pragma unroll
        for (int i = 0; i < 8; i++) {
            int q = i * 256 + tid;
            int tile = q >> 10;
            int qq = q & 1023;
            int r = qq >> 3, c16 = (qq & 7) << 4;
            uint32_t dst = sbase + tile * TILE_BYTES + sw_off(r, c16);
            const void* src = (const char*)(srcs[tile] + (size_t)r * Dd + d0) + c16;
            asm volatile("cp.async.cg.shared.global [%0], [%1], 16;" :: "r"(dst), "l"(src));
        }
        asm volatile("cp.async.commit_group;" ::: "memory");
    };

    float acc[4][4][4];
#pragma unroll
    for (int a = 0; a < 4; a++)
#pragma unroll
        for (int b = 0; b < 4; b++)
#pragma unroll
            for (int c = 0; c < 4; c++) acc[a][b][c] = 0.f;

    stage_load(0, 0);
    stage_load(1, 1);

    for (int kt = 0; kt < 32; kt++) {
        asm volatile("cp.async.wait_group 1;" ::: "memory");
        __syncthreads();
        if (kt + 2 < 32) stage_load(kt + 2, (kt + 2) % 3);

        const uint32_t sb  = smbase + (kt % 3) * STAGE_BYTES;
        const uint32_t a0b = sb;
        const uint32_t b0b = sb + TILE_BYTES;

#pragma unroll
        for (int kk = 0; kk < 4; kk++) {
            const int cba = kk * 32 + ((lane >> 4) & 1) * 16;
            const int cbb = kk * 32 + ((lane >> 3) & 1) * 16;
            uint32_t a0f[4][4];
#pragma unroll
            for (int mi = 0; mi < 4; mi++) {
                int r = mw * 64 + mi * 16 + (lane & 15);
                LDSM4(a0f[mi], a0b + sw_off(r, cba));
            }
            uint32_t b0f[2][4];
#pragma unroll
            for (int nj = 0; nj < 2; nj++) {
                int r = nw * 32 + nj * 16 + (lane & 7) + ((lane >> 4) & 1) * 8;
                LDSM4(b0f[nj], b0b + sw_off(r, cbb));
            }
#pragma unroll
            for (int mi = 0; mi < 4; mi++)
#pragma unroll
                for (int ni = 0; ni < 4; ni++) {
                    const uint32_t* p0 = &b0f[ni >> 1][(ni & 1) * 2];
                    MMA16816(acc[mi][ni], a0f[mi], p0[0], p0[1]);
                }
        }
    }

#pragma unroll
    for (int mi = 0; mi < 4; mi++) {
        int rbase = n0 + mw * 64 + mi * 16 + (lane >> 2);
#pragma unroll
        for (int ni = 0; ni < 4; ni++) {
            int c = k0 + nw * 32 + ni * 8 + (lane & 3) * 2;
            *(float2*)&g_dots[(size_t)rbase * Kk + c]       = make_float2(acc[mi][ni][0], acc[mi][ni][1]);
            *(float2*)&g_dots[(size_t)(rbase + 8) * Kk + c] = make_float2(acc[mi][ni][2], acc[mi][ni][3]);
        }
    }
}

// ---------------------------------------------------------------------------
// fused select: approx argmin + margin shortlist; cnt==1 fast path (no exact
// eval needed — margin >> approx noise); else exact fp32 refine. warp per row.
// ---------------------------------------------------------------------------
__global__ void __launch_bounds__(256) k_select(const float* __restrict__ cb) {
    int w = threadIdx.x >> 5, lane = threadIdx.x & 31;
    int n = blockIdx.x * 8 + w;
    float S = g_S[n];
    const float* row = g_dots + (size_t)n * Kk;

    // approx quantized distances (identical arithmetic to validated k_argmin)
    float v[16];
    float best = 3.4e38f;
#pragma unroll
    for (int i = 0; i < 16; i++) {
        int k = i * 32 + lane;
        float m  = __fmul_rn(2.0f, __ldcs(&row[k]));
        float v1 = __fadd_rn(S, -m);
        v[i] = __fadd_rn(v1, g_C2[k]);
        best = fminf(best, v[i]);
    }
#pragma unroll
    for (int off = 16; off; off >>= 1)
        best = fminf(best, __shfl_xor_sync(0xFFFFFFFFu, best, off));
    float thr = best + MARGIN;

    // shortlist census
    unsigned masks[16];
    int total = 0;
#pragma unroll
    for (int i = 0; i < 16; i++) {
        masks[i] = __ballot_sync(0xFFFFFFFFu, v[i] <= thr);
        total += __popc(masks[i]);
    }

    if (total == 1) {
        // unique candidate within margin: it is the argmin; no exact eval.
        if (lane == 0) {
            int kk = 0;
#pragma unroll
            for (int i = 0; i < 16; i++)
                if (masks[i]) kk = i * 32 + (__ffs(masks[i]) - 1);
            g_idx[n] = kk;
        }
        return;
    }

    // exact re-evaluation of every candidate within margin (validated path)
    const float* arow = g_at + (size_t)n * Dd;
    unsigned long long bkey = 0xFFFFFFFFFFFFFFFFull;
#pragma unroll
    for (int i = 0; i < 16; i++) {
        unsigned mask = masks[i];
        while (mask) {
            int src = __ffs(mask) - 1;
            mask &= mask - 1;
            int k = i * 32 + src;
            const float* brow = cb + (size_t)k * Dd;
            float acc = 0.f;
#pragma unroll
            for (int j = 0; j < 16; j++) {
                float4 a = *(const float4*)(arow + j * 128 + lane * 4);
                float4 b = *(const float4*)(brow + j * 128 + lane * 4);
                acc = fmaf(a.x, b.x, acc);
                acc = fmaf(a.y, b.y, acc);
                acc = fmaf(a.z, b.z, acc);
                acc = fmaf(a.w, b.w, acc);
            }
#pragma unroll
            for (int off = 16; off; off >>= 1)
                acc += __shfl_xor_sync(0xFFFFFFFFu, acc, off);
            float vv = __fadd_rn(__fadd_rn(S, -__fmul_rn(2.0f, acc)), g_C2[k]);
            unsigned long long kk =
                ((unsigned long long)__float_as_uint(vv) << 32) | (unsigned)k;
            if (kk < bkey) bkey = kk;
        }
    }
    if (lane == 0) g_idx[n] = (int)(bkey & 0xFFFFFFFFull);
}

// ---------------------------------------------------------------------------
// scatter + conv, no atomics: block = 32 t, double-buffered 64-d staging,
// streaming stores for outputs
// ---------------------------------------------------------------------------
__global__ void __launch_bounds__(256) k_scatter2(const float* __restrict__ z,
                                                  const float* __restrict__ cb,
                                                  const float* __restrict__ cw,
                                                  const float* __restrict__ cbias,
                                                  float* __restrict__ out) {
    __shared__ int   sidx[32];
    __shared__ float scb[2][32][65];
    __shared__ float r1[8][33], r2[8][33];

    int b  = blockIdx.y;
    int t0 = blockIdx.x * 32;
    int w = threadIdx.x >> 5, lane = threadIdx.x & 31;

    if (threadIdx.x < 32)
        sidx[threadIdx.x] = g_idx[b * Tt + t0 + threadIdx.x];
    __syncthreads();

    // prefetch tile 0
#pragma unroll
    for (int i = 0; i < 8; i++) {
        int e = i * 256 + threadIdx.x;
        int row = e >> 6, dc = e & 63;
        scb[0][row][dc] = cb[(size_t)sidx[row] * Dd + dc];
    }
    __syncthreads();

    float acc1 = 0.f, acc2 = 0.f;
    for (int dt = 0; dt < 32; dt++) {
        int d0 = dt * 64;
        int cur = dt & 1;
        if (dt + 1 < 32) {
            int d1 = d0 + 64;
#pragma unroll
            for (int i = 0; i < 8; i++) {
                int e = i * 256 + threadIdx.x;
                int row = e >> 6, dc = e & 63;
                scb[cur ^ 1][row][dc] = cb[(size_t)sidx[row] * Dd + d1 + dc];
            }
        }

        const float* zp = z   + (size_t)b * Dd * Tt + (size_t)d0 * Tt + t0 + lane;
        float*       o1 = out + (size_t)b * Dd * Tt + (size_t)d0 * Tt + t0 + lane;
        float*       o3 = o1 + BAR_OFF;
#pragma unroll
        for (int j = 0; j < 8; j++) {
            int dl = w * 8 + j;
            float q  = scb[cur][lane][dl];
            float zv = __ldcs(&zp[(size_t)dl * Tt]);
            float dqz = __fadd_rn(q, -zv);
            float zq  = __fadd_rn(zv, dqz);
            __stcs(&o1[(size_t)dl * Tt], zq);
            __stcs(&o3[(size_t)dl * Tt], q);
            float wv = __ldg(cw + d0 + dl);
            acc1 += zq * wv;
            acc2 += q * wv;
        }
        __syncthreads();
    }

    r1[w][lane] = acc1;
    r2[w][lane] = acc2;
    __syncthreads();
    if (w == 0) {
        float bias = __ldg(cbias);
        float s1 = 0.f, s2 = 0.f;
#pragma unroll
        for (int i = 0; i < 8; i++) { s1 += r1[i][lane]; s2 += r2[i][lane]; }
        out[OH1_OFF + b * Tt + t0 + lane] = bias + s1;
        out[OH2_OFF + b * Tt + t0 + lane] = bias + s2;
    }
}

// ---------------------------------------------------------------------------
extern "C" void kernel_launch(void* const* d_in, const int* in_sizes, int n_in,
                              void* d_out, int out_size) {
    const float* z      = (const float*)d_in[0];
    const float* cb     = (const float*)d_in[1];
    const float* conv_w = (const float*)d_in[2];
    const float* conv_b = (const float*)d_in[3];
    float* out = (float*)d_out;

    cudaFuncSetAttribute(k_gemm_mma, cudaFuncAttributeMaxDynamicSharedMemorySize, SM_SZ);

    k_prep_cb<<<Kk, 256>>>(cb);
    k_prep_z_s<<<dim3(Tt / 32, Bb), 256>>>(z);
    k_gemm_mma<<<dim3(Kk / 128, Nn / 128), 256, SM_SZ>>>();
    k_select<<<Nn / 8, 256>>>(cb);
    k_scatter2<<<dim3(Tt / 32, Bb), 256>>>(z, cb, conv_w, conv_b, out);
}

// round 11
// speedup vs baseline: 1.2003x; 1.2003x over previous
#include <cuda_runtime.h>
#include <cuda_bf16.h>
#include <cstdint>

#define Bb 32
#define Dd 2048
#define Tt 512
#define Kk 512
#define Nn (Bb*Tt)            // 16384
#define BDT (Bb*Dd*Tt)        // 33554432
#define OH1_OFF BDT
#define BAR_OFF (BDT + Nn)
#define OH2_OFF (2*BDT + Nn)
#define MARGIN 2e-3f

// ---------------- scratch (device globals; allocation-free) ----------------
__device__ __nv_bfloat16 g_a0[(size_t)Nn * Dd];   // z bf16, n-major
__device__ float         g_at[(size_t)Nn * Dd];   // z fp32, n-major (exact)
__device__ __nv_bfloat16 g_b0[(size_t)Kk * Dd];   // codebook bf16
__device__ float g_dots[(size_t)Nn * Kk];         // approx scores (32 MB)
__device__ float g_S[Nn];
__device__ float g_C2[Kk];
__device__ int   g_idx[Nn];

__device__ __forceinline__ uint32_t smem_u32(const void* p) {
    uint32_t a;
    asm("{ .reg .u64 t; cvta.to.shared.u64 t, %1; cvt.u32.u64 %0, t; }" : "=r"(a) : "l"(p));
    return a;
}
__device__ __forceinline__ uint32_t sw_off(int r, int cbyte) {
    return (uint32_t)(r * 128 + (cbyte ^ ((r & 7) << 4)));
}

#define LDSM4(f, addr) \
    asm volatile("ldmatrix.sync.aligned.m8n8.x4.shared.b16 {%0,%1,%2,%3}, [%4];" \
        : "=r"((f)[0]), "=r"((f)[1]), "=r"((f)[2]), "=r"((f)[3]) : "r"(addr))

#define MMA16816(d, a, br0, br1) \
    asm volatile("mma.sync.aligned.m16n8k16.row.col.f32.bf16.bf16.f32 " \
        "{%0,%1,%2,%3}, {%4,%5,%6,%7}, {%8,%9}, {%0,%1,%2,%3};" \
        : "+f"((d)[0]), "+f"((d)[1]), "+f"((d)[2]), "+f"((d)[3]) \
        : "r"((a)[0]), "r"((a)[1]), "r"((a)[2]), "r"((a)[3]), "r"(br0), "r"(br1))

// ---------------------------------------------------------------------------
// codebook: C2 + bf16 copy (validated)
// ---------------------------------------------------------------------------
__global__ void k_prep_cb(const float* __restrict__ cb) {
    int k = blockIdx.x;
    const float4* row = (const float4*)(cb + (size_t)k * Dd);
    float s = 0.f;
    for (int i = threadIdx.x; i < Dd / 4; i += 256) {
        float4 v = row[i];
        s += v.x * v.x + v.y * v.y + v.z * v.z + v.w * v.w;
        __nv_bfloat16 h[4];
        h[0] = __float2bfloat16(v.x); h[1] = __float2bfloat16(v.y);
        h[2] = __float2bfloat16(v.z); h[3] = __float2bfloat16(v.w);
        *(uint2*)&g_b0[(size_t)k * Dd + 4 * i] = *(uint2*)h;
    }
    __shared__ float sm[256];
    sm[threadIdx.x] = s;
    __syncthreads();
    for (int o = 128; o; o >>= 1) {
        if (threadIdx.x < o) sm[threadIdx.x] += sm[threadIdx.x + o];
        __syncthreads();
    }
    if (threadIdx.x == 0) g_C2[k] = sm[0];
}

// ---------------------------------------------------------------------------
// fused: z (B,D,T) -> n-major bf16 + n-major fp32 + S[n]  (validated)
// ---------------------------------------------------------------------------
__global__ void __launch_bounds__(256) k_prep_z_s(const float* __restrict__ z) {
    __shared__ float s[64][33];
    __shared__ float red[32][9];
    int t0 = blockIdx.x * 32;
    int b  = blockIdx.y;
    const float* zp = z + (size_t)b * Dd * Tt + t0;

    int nl = threadIdx.x >> 3;
    int dc = (threadIdx.x & 7) * 8;
    size_t nrow = (size_t)(b * Tt + t0 + nl) * Dd;
    float Sacc = 0.f;

    for (int dt = 0; dt < 32; dt++) {
        int d0 = dt * 64;
#pragma unroll
        for (int i = 0; i < 8; i++) {
            int e = i * 256 + threadIdx.x;
            int dr = e >> 5, tc = e & 31;
            s[dr][tc] = zp[(size_t)(d0 + dr) * Tt + tc];
        }
        __syncthreads();

        float f[8];
        __nv_bfloat16 h[8];
#pragma unroll
        for (int j = 0; j < 8; j++) {
            f[j] = s[dc + j][nl];
            h[j] = __float2bfloat16(f[j]);
            Sacc += f[j] * f[j];
        }
        *(float4*)&g_at[nrow + d0 + dc]     = *(float4*)(f + 0);
        *(float4*)&g_at[nrow + d0 + dc + 4] = *(float4*)(f + 4);
        *(uint4*)&g_a0[nrow + d0 + dc]      = *(uint4*)h;
        __syncthreads();
    }

    red[nl][threadIdx.x & 7] = Sacc;
    __syncthreads();
    if (threadIdx.x < 32) {
        float t = 0.f;
#pragma unroll
        for (int g = 0; g < 8; g++) t += red[threadIdx.x][g];
        g_S[b * Tt + t0 + threadIdx.x] = t;
    }
}

// ---------------------------------------------------------------------------
// single-pass bf16 mma.sync GEMM -> g_dots  (exact R4/R7/R9 kernel, validated)
// ---------------------------------------------------------------------------
#define TILE_BYTES 16384
#define STAGE_BYTES (2*TILE_BYTES)
#define SM_SZ (3*STAGE_BYTES)      // 98304

__global__ void __launch_bounds__(256) k_gemm_mma() {
    extern __shared__ char sm[];
    const int tid  = threadIdx.x;
    const int lane = tid & 31, wid = tid >> 5;
    const int mw = wid & 1, nw = wid >> 1;
    const int n0 = blockIdx.y * 128;
    const int k0 = blockIdx.x * 128;

    const __nv_bfloat16* srcs[2];
    srcs[0] = g_a0 + (size_t)n0 * Dd;
    srcs[1] = g_b0 + (size_t)k0 * Dd;

    const uint32_t smbase = smem_u32(sm);

    auto stage_load = [&](int kt, int slot) {
        const int d0 = kt * 64;
        const uint32_t sbase = smbase + slot * STAGE_BYTES;
#pragma unroll
        for (int i = 0; i < 8; i++) {
            int q = i * 256 + tid;
            int tile = q >> 10;
            int qq = q & 1023;
            int r = qq >> 3, c16 = (qq & 7) << 4;
            uint32_t dst = sbase + tile * TILE_BYTES + sw_off(r, c16);
            const void* src = (const char*)(srcs[tile] + (size_t)r * Dd + d0) + c16;
            asm volatile("cp.async.cg.shared.global [%0], [%1], 16;" :: "r"(dst), "l"(src));
        }
        asm volatile("cp.async.commit_group;" ::: "memory");
    };

    float acc[4][4][4];
#pragma unroll
    for (int a = 0; a < 4; a++)
#pragma unroll
        for (int b = 0; b < 4; b++)
#pragma unroll
            for (int c = 0; c < 4; c++) acc[a][b][c] = 0.f;

    stage_load(0, 0);
    stage_load(1, 1);

    for (int kt = 0; kt < 32; kt++) {
        asm volatile("cp.async.wait_group 1;" ::: "memory");
        __syncthreads();
        if (kt + 2 < 32) stage_load(kt + 2, (kt + 2) % 3);

        const uint32_t sb  = smbase + (kt % 3) * STAGE_BYTES;
        const uint32_t a0b = sb;
        const uint32_t b0b = sb + TILE_BYTES;

#pragma unroll
        for (int kk = 0; kk < 4; kk++) {
            const int cba = kk * 32 + ((lane >> 4) & 1) * 16;
            const int cbb = kk * 32 + ((lane >> 3) & 1) * 16;
            uint32_t a0f[4][4];
#pragma unroll
            for (int mi = 0; mi < 4; mi++) {
                int r = mw * 64 + mi * 16 + (lane & 15);
                LDSM4(a0f[mi], a0b + sw_off(r, cba));
            }
            uint32_t b0f[2][4];
#pragma unroll
            for (int nj = 0; nj < 2; nj++) {
                int r = nw * 32 + nj * 16 + (lane & 7) + ((lane >> 4) & 1) * 8;
                LDSM4(b0f[nj], b0b + sw_off(r, cbb));
            }
#pragma unroll
            for (int mi = 0; mi < 4; mi++)
#pragma unroll
                for (int ni = 0; ni < 4; ni++) {
                    const uint32_t* p0 = &b0f[ni >> 1][(ni & 1) * 2];
                    MMA16816(acc[mi][ni], a0f[mi], p0[0], p0[1]);
                }
        }
    }

#pragma unroll
    for (int mi = 0; mi < 4; mi++) {
        int rbase = n0 + mw * 64 + mi * 16 + (lane >> 2);
#pragma unroll
        for (int ni = 0; ni < 4; ni++) {
            int c = k0 + nw * 32 + ni * 8 + (lane & 3) * 2;
            *(float2*)&g_dots[(size_t)rbase * Kk + c]       = make_float2(acc[mi][ni][0], acc[mi][ni][1]);
            *(float2*)&g_dots[(size_t)(rbase + 8) * Kk + c] = make_float2(acc[mi][ni][2], acc[mi][ni][3]);
        }
    }
}

// ---------------------------------------------------------------------------
// fused select: approx argmin + margin shortlist; cnt==1 fast path (validated
// in R10: identical indices, 22.9us); plain loads (streaming hints reverted)
// ---------------------------------------------------------------------------
__global__ void __launch_bounds__(256) k_select(const float* __restrict__ cb) {
    int w = threadIdx.x >> 5, lane = threadIdx.x & 31;
    int n = blockIdx.x * 8 + w;
    float S = g_S[n];
    const float* row = g_dots + (size_t)n * Kk;

    // approx quantized distances (identical arithmetic to validated k_argmin)
    float v[16];
    float best = 3.4e38f;
#pragma unroll
    for (int i = 0; i < 16; i++) {
        int k = i * 32 + lane;
        float m  = __fmul_rn(2.0f, row[k]);
        float v1 = __fadd_rn(S, -m);
        v[i] = __fadd_rn(v1, g_C2[k]);
        best = fminf(best, v[i]);
    }
#pragma unroll
    for (int off = 16; off; off >>= 1)
        best = fminf(best, __shfl_xor_sync(0xFFFFFFFFu, best, off));
    float thr = best + MARGIN;

    // shortlist census
    unsigned masks[16];
    int total = 0;
#pragma unroll
    for (int i = 0; i < 16; i++) {
        masks[i] = __ballot_sync(0xFFFFFFFFu, v[i] <= thr);
        total += __popc(masks[i]);
    }

    if (total == 1) {
        // unique candidate within margin: it is the argmin; no exact eval.
        if (lane == 0) {
            int kk = 0;
#pragma unroll
            for (int i = 0; i < 16; i++)
                if (masks[i]) kk = i * 32 + (__ffs(masks[i]) - 1);
            g_idx[n] = kk;
        }
        return;
    }

    // exact re-evaluation of every candidate within margin (validated path)
    const float* arow = g_at + (size_t)n * Dd;
    unsigned long long bkey = 0xFFFFFFFFFFFFFFFFull;
#pragma unroll
    for (int i = 0; i < 16; i++) {
        unsigned mask = masks[i];
        while (mask) {
            int src = __ffs(mask) - 1;
            mask &= mask - 1;
            int k = i * 32 + src;
            const float* brow = cb + (size_t)k * Dd;
            float acc = 0.f;
#pragma unroll
            for (int j = 0; j < 16; j++) {
                float4 a = *(const float4*)(arow + j * 128 + lane * 4);
                float4 b = *(const float4*)(brow + j * 128 + lane * 4);
                acc = fmaf(a.x, b.x, acc);
                acc = fmaf(a.y, b.y, acc);
                acc = fmaf(a.z, b.z, acc);
                acc = fmaf(a.w, b.w, acc);
            }
#pragma unroll
            for (int off = 16; off; off >>= 1)
                acc += __shfl_xor_sync(0xFFFFFFFFu, acc, off);
            float vv = __fadd_rn(__fadd_rn(S, -__fmul_rn(2.0f, acc)), g_C2[k]);
            unsigned long long kk =
                ((unsigned long long)__float_as_uint(vv) << 32) | (unsigned)k;
            if (kk < bkey) bkey = kk;
        }
    }
    if (lane == 0) g_idx[n] = (int)(bkey & 0xFFFFFFFFull);
}

// ---------------------------------------------------------------------------
// scatter + conv, no atomics: block = 32 t, double-buffered 64-d staging
// (exact R9 kernel — no streaming hints)
// ---------------------------------------------------------------------------
__global__ void __launch_bounds__(256) k_scatter2(const float* __restrict__ z,
                                                  const float* __restrict__ cb,
                                                  const float* __restrict__ cw,
                                                  const float* __restrict__ cbias,
                                                  float* __restrict__ out) {
    __shared__ int   sidx[32];
    __shared__ float scb[2][32][65];
    __shared__ float r1[8][33], r2[8][33];

    int b  = blockIdx.y;
    int t0 = blockIdx.x * 32;
    int w = threadIdx.x >> 5, lane = threadIdx.x & 31;

    if (threadIdx.x < 32)
        sidx[threadIdx.x] = g_idx[b * Tt + t0 + threadIdx.x];
    __syncthreads();

    // prefetch tile 0
#pragma unroll
    for (int i = 0; i < 8; i++) {
        int e = i * 256 + threadIdx.x;
        int row = e >> 6, dc = e & 63;
        scb[0][row][dc] = cb[(size_t)sidx[row] * Dd + dc];
    }
    __syncthreads();

    float acc1 = 0.f, acc2 = 0.f;
    for (int dt = 0; dt < 32; dt++) {
        int d0 = dt * 64;
        int cur = dt & 1;
        if (dt + 1 < 32) {
            int d1 = d0 + 64;
#pragma unroll
            for (int i = 0; i < 8; i++) {
                int e = i * 256 + threadIdx.x;
                int row = e >> 6, dc = e & 63;
                scb[cur ^ 1][row][dc] = cb[(size_t)sidx[row] * Dd + d1 + dc];
            }
        }

        const float* zp = z   + (size_t)b * Dd * Tt + (size_t)d0 * Tt + t0 + lane;
        float*       o1 = out + (size_t)b * Dd * Tt + (size_t)d0 * Tt + t0 + lane;
        float*       o3 = o1 + BAR_OFF;
#pragma unroll
        for (int j = 0; j < 8; j++) {
            int dl = w * 8 + j;
            float q  = scb[cur][lane][dl];
            float zv = zp[(size_t)dl * Tt];
            float dqz = __fadd_rn(q, -zv);
            float zq  = __fadd_rn(zv, dqz);
            o1[(size_t)dl * Tt] = zq;
            o3[(size_t)dl * Tt] = q;
            float wv = __ldg(cw + d0 + dl);
            acc1 += zq * wv;
            acc2 += q * wv;
        }
        __syncthreads();
    }

    r1[w][lane] = acc1;
    r2[w][lane] = acc2;
    __syncthreads();
    if (w == 0) {
        float bias = __ldg(cbias);
        float s1 = 0.f, s2 = 0.f;
#pragma unroll
        for (int i = 0; i < 8; i++) { s1 += r1[i][lane]; s2 += r2[i][lane]; }
        out[OH1_OFF + b * Tt + t0 + lane] = bias + s1;
        out[OH2_OFF + b * Tt + t0 + lane] = bias + s2;
    }
}

// ---------------------------------------------------------------------------
extern "C" void kernel_launch(void* const* d_in, const int* in_sizes, int n_in,
                              void* d_out, int out_size) {
    const float* z      = (const float*)d_in[0];
    const float* cb     = (const float*)d_in[1];
    const float* conv_w = (const float*)d_in[2];
    const float* conv_b = (const float*)d_in[3];
    float* out = (float*)d_out;

    cudaFuncSetAttribute(k_gemm_mma, cudaFuncAttributeMaxDynamicSharedMemorySize, SM_SZ);

    k_prep_cb<<<Kk, 256>>>(cb);
    k_prep_z_s<<<dim3(Tt / 32, Bb), 256>>>(z);
    k_gemm_mma<<<dim3(Kk / 128, Nn / 128), 256, SM_SZ>>>();
    k_select<<<Nn / 8, 256>>>(cb);
    k_scatter2<<<dim3(Tt / 32, Bb), 256>>>(z, cb, conv_w, conv_b, out);
}